// round 1
// baseline (speedup 1.0000x reference)
#include <cuda_runtime.h>
#include <cstddef>

#define BB 2
#define TT 2048
#define DD 1024
#define HH 16
#define HD 64

// Scratch (allocation-free): qkv = [B,T,3,H,HD] fp32 (50.3MB), y = [B,T,D] fp32 (16.8MB)
__device__ float g_qkv[(size_t)BB * TT * 3 * DD];
__device__ float g_y[(size_t)BB * TT * DD];

// ---------------------------------------------------------------------------
// Tiled GEMM: C[M,N] = A[M,K] @ B[N,K]^T + bias[N]
// BM=BN=128, BK=16, 256 threads, 8x8 micro-tile per thread.
// Requires M%128==0, N%128==0, K%16==0 (true for all our shapes).
// ---------------------------------------------------------------------------
__global__ void __launch_bounds__(256) gemm_abt_bias(
    const float* __restrict__ A, const float* __restrict__ B,
    const float* __restrict__ bias, float* __restrict__ C,
    int M, int N, int K)
{
    __shared__ float As[16][132];  // [k][m], pad 4 to cut transpose-store conflicts
    __shared__ float Bs[16][132];  // [k][n]

    const int tid = threadIdx.x;
    const int tx = tid & 15;
    const int ty = tid >> 4;
    const int row0 = blockIdx.y * 128;
    const int col0 = blockIdx.x * 128;

    float acc[8][8];
    #pragma unroll
    for (int i = 0; i < 8; ++i)
        #pragma unroll
        for (int j = 0; j < 8; ++j) acc[i][j] = 0.f;

    for (int k0 = 0; k0 < K; k0 += 16) {
        #pragma unroll
        for (int it = 0; it < 2; ++it) {
            int f  = tid + it * 256;       // 0..511 float4 slots
            int r  = f >> 2;               // tile row 0..127
            int c4 = (f & 3) << 2;         // k offset 0,4,8,12
            float4 va = *reinterpret_cast<const float4*>(
                A + (size_t)(row0 + r) * K + k0 + c4);
            As[c4 + 0][r] = va.x; As[c4 + 1][r] = va.y;
            As[c4 + 2][r] = va.z; As[c4 + 3][r] = va.w;
            float4 vb = *reinterpret_cast<const float4*>(
                B + (size_t)(col0 + r) * K + k0 + c4);
            Bs[c4 + 0][r] = vb.x; Bs[c4 + 1][r] = vb.y;
            Bs[c4 + 2][r] = vb.z; Bs[c4 + 3][r] = vb.w;
        }
        __syncthreads();

        #pragma unroll
        for (int k = 0; k < 16; ++k) {
            float a[8], b[8];
            *(float4*)&a[0] = *(const float4*)&As[k][ty * 8];
            *(float4*)&a[4] = *(const float4*)&As[k][ty * 8 + 4];
            *(float4*)&b[0] = *(const float4*)&Bs[k][tx * 8];
            *(float4*)&b[4] = *(const float4*)&Bs[k][tx * 8 + 4];
            #pragma unroll
            for (int i = 0; i < 8; ++i)
                #pragma unroll
                for (int j = 0; j < 8; ++j)
                    acc[i][j] = fmaf(a[i], b[j], acc[i][j]);
        }
        __syncthreads();
    }

    #pragma unroll
    for (int i = 0; i < 8; ++i) {
        int r = row0 + ty * 8 + i;
        #pragma unroll
        for (int j = 0; j < 8; j += 4) {
            int c = col0 + tx * 8 + j;
            float4 o;
            o.x = acc[i][j + 0] + bias[c + 0];
            o.y = acc[i][j + 1] + bias[c + 1];
            o.z = acc[i][j + 2] + bias[c + 2];
            o.w = acc[i][j + 3] + bias[c + 3];
            *reinterpret_cast<float4*>(C + (size_t)r * N + c) = o;
        }
    }
}

// ---------------------------------------------------------------------------
// Fused flash attention (fp32, online softmax).
// Grid: (T/64, B*H). Block: 256 threads (16x16). Each block: 64 queries.
// smem: Qt[d][q], Kt[d][k], Vs[k][d], Pt[k][q], each 64x68 floats.
// Thread (ty,tx) owns rows ty*4..+3 (queries) x cols tx*4..+3 (keys or dims).
// ---------------------------------------------------------------------------
__global__ void __launch_bounds__(256) attn_kernel(
    const float* __restrict__ qkv, const int* __restrict__ mask,
    float* __restrict__ y)
{
    extern __shared__ float sm[];
    const int PAD = 68;
    float* Qt = sm;                 // [64 d][68] (transposed, pre-scaled)
    float* Kt = sm + 64 * PAD;      // [64 d][68] (transposed)
    float* Vs = sm + 2 * 64 * PAD;  // [64 k][68] (natural)
    float* Pt = sm + 3 * 64 * PAD;  // [64 k][68] (transposed probs)

    const int tid = threadIdx.x;
    const int tx = tid & 15;
    const int ty = tid >> 4;
    const int q0 = blockIdx.x * 64;
    const int b  = blockIdx.y >> 4;
    const int h  = blockIdx.y & 15;
    const float scale = 0.125f;  // 1/sqrt(64)

    const size_t row_stride = 3 * DD;
    const size_t q_base = (size_t)(b * TT + q0) * row_stride + h * HD;

    // Load Q tile transposed, pre-scaled
    #pragma unroll
    for (int it = 0; it < 4; ++it) {
        int f  = tid + it * 256;
        int r  = f >> 4;           // query row 0..63
        int d4 = (f & 15) << 2;    // dim 0..60
        float4 v = *reinterpret_cast<const float4*>(
            qkv + q_base + (size_t)r * row_stride + d4);
        Qt[(d4 + 0) * PAD + r] = v.x * scale;
        Qt[(d4 + 1) * PAD + r] = v.y * scale;
        Qt[(d4 + 2) * PAD + r] = v.z * scale;
        Qt[(d4 + 3) * PAD + r] = v.w * scale;
    }

    float m_i[4], l_i[4], o[4][4];
    #pragma unroll
    for (int i = 0; i < 4; ++i) {
        m_i[i] = -1e30f; l_i[i] = 0.f;
        #pragma unroll
        for (int j = 0; j < 4; ++j) o[i][j] = 0.f;
    }

    for (int kv0 = 0; kv0 < TT; kv0 += 64) {
        const size_t kv_base = (size_t)(b * TT + kv0) * row_stride + h * HD;
        __syncthreads();  // previous O-phase done reading Vs/Pt (and Q-load at iter 0)

        #pragma unroll
        for (int it = 0; it < 4; ++it) {
            int f  = tid + it * 256;
            int r  = f >> 4;
            int d4 = (f & 15) << 2;
            float4 kk = *reinterpret_cast<const float4*>(
                qkv + kv_base + DD + (size_t)r * row_stride + d4);       // s=1 (K)
            Kt[(d4 + 0) * PAD + r] = kk.x;
            Kt[(d4 + 1) * PAD + r] = kk.y;
            Kt[(d4 + 2) * PAD + r] = kk.z;
            Kt[(d4 + 3) * PAD + r] = kk.w;
            float4 vv = *reinterpret_cast<const float4*>(
                qkv + kv_base + 2 * DD + (size_t)r * row_stride + d4);   // s=2 (V)
            *reinterpret_cast<float4*>(Vs + r * PAD + d4) = vv;
        }
        __syncthreads();

        // S = (Q*scale) @ K^T  (4x4 micro-tile)
        float s[4][4];
        #pragma unroll
        for (int i = 0; i < 4; ++i)
            #pragma unroll
            for (int j = 0; j < 4; ++j) s[i][j] = 0.f;
        #pragma unroll
        for (int d = 0; d < 64; ++d) {
            float a[4], bb[4];
            *(float4*)a  = *(const float4*)&Qt[d * PAD + ty * 4];
            *(float4*)bb = *(const float4*)&Kt[d * PAD + tx * 4];
            #pragma unroll
            for (int i = 0; i < 4; ++i)
                #pragma unroll
                for (int j = 0; j < 4; ++j)
                    s[i][j] = fmaf(a[i], bb[j], s[i][j]);
        }

        // Apply mask (mask==0 -> -inf)
        #pragma unroll
        for (int i = 0; i < 4; ++i) {
            const int* mrow = mask + (size_t)(q0 + ty * 4 + i) * TT + kv0 + tx * 4;
            #pragma unroll
            for (int j = 0; j < 4; ++j)
                if (mrow[j] == 0) s[i][j] = -1e30f;
        }

        // Online softmax per query row (reduce across the 16 tx lanes)
        #pragma unroll
        for (int i = 0; i < 4; ++i) {
            float rm = fmaxf(fmaxf(s[i][0], s[i][1]), fmaxf(s[i][2], s[i][3]));
            #pragma unroll
            for (int off = 8; off > 0; off >>= 1)
                rm = fmaxf(rm, __shfl_xor_sync(0xffffffffu, rm, off, 16));
            float m_new = fmaxf(m_i[i], rm);
            float corr  = __expf(m_i[i] - m_new);
            float psum  = 0.f;
            #pragma unroll
            for (int j = 0; j < 4; ++j) {
                float p = __expf(s[i][j] - m_new);
                s[i][j] = p;
                psum += p;
            }
            #pragma unroll
            for (int off = 8; off > 0; off >>= 1)
                psum += __shfl_xor_sync(0xffffffffu, psum, off, 16);
            l_i[i] = l_i[i] * corr + psum;
            m_i[i] = m_new;
            #pragma unroll
            for (int j = 0; j < 4; ++j) o[i][j] *= corr;
        }

        // Stage P transposed for the O GEMM
        #pragma unroll
        for (int i = 0; i < 4; ++i)
            #pragma unroll
            for (int j = 0; j < 4; ++j)
                Pt[(tx * 4 + j) * PAD + ty * 4 + i] = s[i][j];
        __syncthreads();

        // O += P @ V
        #pragma unroll
        for (int kk = 0; kk < 64; ++kk) {
            float a[4], bb[4];
            *(float4*)a  = *(const float4*)&Pt[kk * PAD + ty * 4];
            *(float4*)bb = *(const float4*)&Vs[kk * PAD + tx * 4];
            #pragma unroll
            for (int i = 0; i < 4; ++i)
                #pragma unroll
                for (int j = 0; j < 4; ++j)
                    o[i][j] = fmaf(a[i], bb[j], o[i][j]);
        }
    }

    // Epilogue: normalize and write y[b, q, h*64 + d]
    #pragma unroll
    for (int i = 0; i < 4; ++i) {
        float inv = 1.f / l_i[i];
        float4 ov;
        ov.x = o[i][0] * inv; ov.y = o[i][1] * inv;
        ov.z = o[i][2] * inv; ov.w = o[i][3] * inv;
        size_t idx = (size_t)(b * TT + q0 + ty * 4 + i) * DD + h * HD + tx * 4;
        *reinterpret_cast<float4*>(y + idx) = ov;
    }
}

// ---------------------------------------------------------------------------
extern "C" void kernel_launch(void* const* d_in, const int* in_sizes, int n_in,
                              void* d_out, int out_size)
{
    const float* x     = (const float*)d_in[0];
    const int*   mask  = (const int*)d_in[1];
    const float* w_qkv = (const float*)d_in[2];
    const float* b_qkv = (const float*)d_in[3];
    const float* w_out = (const float*)d_in[4];
    const float* b_out = (const float*)d_in[5];
    float* out = (float*)d_out;

    float* qkv = nullptr;
    float* y   = nullptr;
    cudaGetSymbolAddress((void**)&qkv, g_qkv);
    cudaGetSymbolAddress((void**)&y, g_y);

    const int M = BB * TT;  // 4096

    // 1) QKV projection: [4096,1024] @ [3072,1024]^T + b_qkv
    gemm_abt_bias<<<dim3(3 * DD / 128, M / 128), 256>>>(
        x, w_qkv, b_qkv, qkv, M, 3 * DD, DD);

    // 2) Fused flash attention
    const int attn_smem = 4 * 64 * 68 * (int)sizeof(float);  // 69632 B
    cudaFuncSetAttribute(attn_kernel,
                         cudaFuncAttributeMaxDynamicSharedMemorySize, attn_smem);
    attn_kernel<<<dim3(TT / 64, BB * HH), 256, attn_smem>>>(qkv, mask, y);

    // 3) Output projection: [4096,1024] @ [1024,1024]^T + b_out
    gemm_abt_bias<<<dim3(DD / 128, M / 128), 256>>>(
        y, w_out, b_out, out, M, DD, DD);
}

// round 3
// speedup vs baseline: 1.2846x; 1.2846x over previous
#include <cuda_runtime.h>
#include <cuda_bf16.h>
#include <cstdint>
#include <cstddef>

#define BB 2
#define TT 2048
#define DD 1024
#define HH 16
#define HD 64
#define MM (BB*TT)

// ---------------- scratch (allocation-free) ----------------
__device__ float g_qkv[(size_t)MM * 3 * DD];
__device__ float g_y[(size_t)MM * DD];
__device__ __nv_bfloat16 g_x_hi[(size_t)MM * DD];
__device__ __nv_bfloat16 g_x_lo[(size_t)MM * DD];
__device__ __nv_bfloat16 g_wqkv_hi[(size_t)3 * DD * DD];
__device__ __nv_bfloat16 g_wqkv_lo[(size_t)3 * DD * DD];
__device__ __nv_bfloat16 g_wout_hi[(size_t)DD * DD];
__device__ __nv_bfloat16 g_wout_lo[(size_t)DD * DD];
__device__ __nv_bfloat16 g_y_hi[(size_t)MM * DD];
__device__ __nv_bfloat16 g_y_lo[(size_t)MM * DD];

// ---------------- base-target PTX helpers (no tcgen05!) ----------------
__device__ __forceinline__ uint32_t smem_u32(const void* p) {
    uint32_t a;
    asm("{ .reg .u64 t; cvta.to.shared.u64 t, %1; cvt.u32.u64 %0, t; }"
        : "=r"(a) : "l"(p));
    return a;
}
__device__ __forceinline__ void cp_async16(uint32_t dst, const void* src) {
    asm volatile("cp.async.cg.shared.global [%0], [%1], 16;"
                 :: "r"(dst), "l"(src) : "memory");
}
__device__ __forceinline__ void cp_commit() {
    asm volatile("cp.async.commit_group;" ::: "memory");
}
__device__ __forceinline__ void cp_wait1() {
    asm volatile("cp.async.wait_group 1;" ::: "memory");
}
__device__ __forceinline__ void ldsm_x4(uint32_t addr, uint32_t r[4]) {
    asm volatile("ldmatrix.sync.aligned.m8n8.x4.shared.b16 {%0,%1,%2,%3}, [%4];"
                 : "=r"(r[0]), "=r"(r[1]), "=r"(r[2]), "=r"(r[3]) : "r"(addr));
}
__device__ __forceinline__ void mma_bf16(float d[4], const uint32_t a[4],
                                         uint32_t b0, uint32_t b1) {
    asm volatile(
        "mma.sync.aligned.m16n8k16.row.col.f32.bf16.bf16.f32 "
        "{%0,%1,%2,%3}, {%4,%5,%6,%7}, {%8,%9}, {%0,%1,%2,%3};"
        : "+f"(d[0]), "+f"(d[1]), "+f"(d[2]), "+f"(d[3])
        : "r"(a[0]), "r"(a[1]), "r"(a[2]), "r"(a[3]), "r"(b0), "r"(b1));
}

// ---------------------------------------------------------------------------
// Split fp32 -> (hi, lo) bf16.
// ---------------------------------------------------------------------------
__global__ void __launch_bounds__(256) split_bf16(
    const float* __restrict__ src,
    __nv_bfloat16* __restrict__ hi, __nv_bfloat16* __restrict__ lo, int n4)
{
    int i = blockIdx.x * blockDim.x + threadIdx.x;
    if (i >= n4) return;
    float4 v = reinterpret_cast<const float4*>(src)[i];
    __nv_bfloat16 h0 = __float2bfloat16(v.x);
    __nv_bfloat16 h1 = __float2bfloat16(v.y);
    __nv_bfloat16 h2 = __float2bfloat16(v.z);
    __nv_bfloat16 h3 = __float2bfloat16(v.w);
    __nv_bfloat16 l0 = __float2bfloat16(v.x - __bfloat162float(h0));
    __nv_bfloat16 l1 = __float2bfloat16(v.y - __bfloat162float(h1));
    __nv_bfloat16 l2 = __float2bfloat16(v.z - __bfloat162float(h2));
    __nv_bfloat16 l3 = __float2bfloat16(v.w - __bfloat162float(h3));
    reinterpret_cast<__nv_bfloat162*>(hi)[i * 2 + 0] = __nv_bfloat162(h0, h1);
    reinterpret_cast<__nv_bfloat162*>(hi)[i * 2 + 1] = __nv_bfloat162(h2, h3);
    reinterpret_cast<__nv_bfloat162*>(lo)[i * 2 + 0] = __nv_bfloat162(l0, l1);
    reinterpret_cast<__nv_bfloat162*>(lo)[i * 2 + 1] = __nv_bfloat162(l2, l3);
}

// ---------------------------------------------------------------------------
// Split-bf16 tensor-core GEMM via mma.sync:
//   C[M,N] = (Ah+Al)[M,K] @ (Bh+Bl)[N,K]^T + bias[N]   (drops Al@Bl)
// 128x128 CTA tile, BK=32, 8 warps (2x4), warp tile 64x32.
// Double-buffered cp.async. Requires M%128==0, N%128==0, K%32==0.
// ---------------------------------------------------------------------------
#define LDA 40                      // bf16 elems per smem row (32 + 8 pad)
#define TILE_B (128 * LDA * 2)      // 10240 B per tile
#define BUF_B  (4 * TILE_B)         // Ah, Al, Bh, Bl
#define GEMM_SMEM (2 * BUF_B)       // 81920 B

__global__ void __launch_bounds__(256)
gemm_mma_split(const __nv_bfloat16* __restrict__ Ah, const __nv_bfloat16* __restrict__ Al,
               const __nv_bfloat16* __restrict__ Bh, const __nv_bfloat16* __restrict__ Bl,
               const float* __restrict__ bias, float* __restrict__ C,
               int M, int N, int K)
{
    extern __shared__ __align__(16) char sm[];
    const uint32_t sm_u = smem_u32(sm);

    const int tid  = threadIdx.x;
    const int lane = tid & 31;
    const int wid  = tid >> 5;
    const int wm   = wid & 1;       // warp row (2)
    const int wn   = wid >> 1;      // warp col (4)
    const int row0 = blockIdx.y * 128;
    const int col0 = blockIdx.x * 128;

    // ---- async copy of one K-chunk into buffer b ----
    auto copy_chunk = [&](int ch, int b) {
        const int k0 = ch * 32;
        const uint32_t base = sm_u + b * BUF_B;
        const __nv_bfloat16* srcs[4] = {Ah, Al, Bh, Bl};
        const int rbase[4] = {row0, row0, col0, col0};
        #pragma unroll
        for (int t = 0; t < 4; ++t) {
            #pragma unroll
            for (int it = 0; it < 2; ++it) {
                int idx = tid + it * 256;       // 512 segments of 16B
                int r = idx >> 2;
                int s = idx & 3;
                cp_async16(base + t * TILE_B + r * (LDA * 2) + s * 16,
                           srcs[t] + (size_t)(rbase[t] + r) * K + k0 + s * 8);
            }
        }
    };

    float acc[4][4][4];
    #pragma unroll
    for (int i = 0; i < 4; ++i)
        #pragma unroll
        for (int j = 0; j < 4; ++j)
            #pragma unroll
            for (int r = 0; r < 4; ++r) acc[i][j][r] = 0.f;

    const int nchunk = K / 32;
    copy_chunk(0, 0);
    cp_commit();

    // ldmatrix lane addressing
    const int lr = lane & 15;       // row within 16
    const int lc = lane >> 4;       // k-half (0/1) -> +8 elems

    for (int ch = 0; ch < nchunk; ++ch) {
        if (ch + 1 < nchunk) copy_chunk(ch + 1, (ch + 1) & 1);
        cp_commit();
        cp_wait1();
        __syncthreads();

        const uint32_t base = sm_u + (ch & 1) * BUF_B;
        const uint32_t tAh = base;
        const uint32_t tAl = base + TILE_B;
        const uint32_t tBh = base + 2 * TILE_B;
        const uint32_t tBl = base + 3 * TILE_B;

        #pragma unroll
        for (int kk = 0; kk < 32; kk += 16) {
            uint32_t ah[4][4], al[4][4];
            uint32_t bh[4][2], bl[4][2];
            #pragma unroll
            for (int mi = 0; mi < 4; ++mi) {
                uint32_t off = (uint32_t)((wm * 64 + mi * 16 + lr) * (LDA * 2)
                                          + (lc * 8 + kk) * 2);
                ldsm_x4(tAh + off, ah[mi]);
                ldsm_x4(tAl + off, al[mi]);
            }
            #pragma unroll
            for (int n2 = 0; n2 < 2; ++n2) {
                uint32_t off = (uint32_t)((wn * 32 + n2 * 16 + lr) * (LDA * 2)
                                          + (lc * 8 + kk) * 2);
                uint32_t th[4], tl[4];
                ldsm_x4(tBh + off, th);
                ldsm_x4(tBl + off, tl);
                bh[n2 * 2 + 0][0] = th[0]; bh[n2 * 2 + 0][1] = th[2];
                bh[n2 * 2 + 1][0] = th[1]; bh[n2 * 2 + 1][1] = th[3];
                bl[n2 * 2 + 0][0] = tl[0]; bl[n2 * 2 + 0][1] = tl[2];
                bl[n2 * 2 + 1][0] = tl[1]; bl[n2 * 2 + 1][1] = tl[3];
            }
            #pragma unroll
            for (int mi = 0; mi < 4; ++mi)
                #pragma unroll
                for (int nj = 0; nj < 4; ++nj) {
                    mma_bf16(acc[mi][nj], ah[mi], bh[nj][0], bh[nj][1]);
                    mma_bf16(acc[mi][nj], ah[mi], bl[nj][0], bl[nj][1]);
                    mma_bf16(acc[mi][nj], al[mi], bh[nj][0], bh[nj][1]);
                }
        }
        __syncthreads();
    }

    // ---- epilogue: c-fragment layout -> global, + bias ----
    #pragma unroll
    for (int mi = 0; mi < 4; ++mi) {
        #pragma unroll
        for (int nj = 0; nj < 4; ++nj) {
            int col = col0 + wn * 32 + nj * 8 + (lane & 3) * 2;
            float b0 = bias[col], b1 = bias[col + 1];
            #pragma unroll
            for (int h = 0; h < 2; ++h) {
                int row = row0 + wm * 64 + mi * 16 + (lane >> 2) + h * 8;
                float2 o;
                o.x = acc[mi][nj][h * 2 + 0] + b0;
                o.y = acc[mi][nj][h * 2 + 1] + b1;
                *reinterpret_cast<float2*>(C + (size_t)row * N + col) = o;
            }
        }
    }
}

// ---------------------------------------------------------------------------
// Fused flash attention (fp32, online softmax) — unchanged from round 1.
// ---------------------------------------------------------------------------
__global__ void __launch_bounds__(256) attn_kernel(
    const float* __restrict__ qkv, const int* __restrict__ mask,
    float* __restrict__ y)
{
    extern __shared__ float smf[];
    const int PAD = 68;
    float* Qt = smf;
    float* Kt = smf + 64 * PAD;
    float* Vs = smf + 2 * 64 * PAD;
    float* Pt = smf + 3 * 64 * PAD;

    const int tid = threadIdx.x;
    const int tx = tid & 15;
    const int ty = tid >> 4;
    const int q0 = blockIdx.x * 64;
    const int b  = blockIdx.y >> 4;
    const int h  = blockIdx.y & 15;
    const float scale = 0.125f;

    const size_t row_stride = 3 * DD;
    const size_t q_base = (size_t)(b * TT + q0) * row_stride + h * HD;

    #pragma unroll
    for (int it = 0; it < 4; ++it) {
        int f  = tid + it * 256;
        int r  = f >> 4;
        int d4 = (f & 15) << 2;
        float4 v = *reinterpret_cast<const float4*>(
            qkv + q_base + (size_t)r * row_stride + d4);
        Qt[(d4 + 0) * PAD + r] = v.x * scale;
        Qt[(d4 + 1) * PAD + r] = v.y * scale;
        Qt[(d4 + 2) * PAD + r] = v.z * scale;
        Qt[(d4 + 3) * PAD + r] = v.w * scale;
    }

    float m_i[4], l_i[4], o[4][4];
    #pragma unroll
    for (int i = 0; i < 4; ++i) {
        m_i[i] = -1e30f; l_i[i] = 0.f;
        #pragma unroll
        for (int j = 0; j < 4; ++j) o[i][j] = 0.f;
    }

    for (int kv0 = 0; kv0 < TT; kv0 += 64) {
        const size_t kv_base = (size_t)(b * TT + kv0) * row_stride + h * HD;
        __syncthreads();

        #pragma unroll
        for (int it = 0; it < 4; ++it) {
            int f  = tid + it * 256;
            int r  = f >> 4;
            int d4 = (f & 15) << 2;
            float4 kk = *reinterpret_cast<const float4*>(
                qkv + kv_base + DD + (size_t)r * row_stride + d4);
            Kt[(d4 + 0) * PAD + r] = kk.x;
            Kt[(d4 + 1) * PAD + r] = kk.y;
            Kt[(d4 + 2) * PAD + r] = kk.z;
            Kt[(d4 + 3) * PAD + r] = kk.w;
            float4 vv = *reinterpret_cast<const float4*>(
                qkv + kv_base + 2 * DD + (size_t)r * row_stride + d4);
            *reinterpret_cast<float4*>(Vs + r * PAD + d4) = vv;
        }
        __syncthreads();

        float s[4][4];
        #pragma unroll
        for (int i = 0; i < 4; ++i)
            #pragma unroll
            for (int j = 0; j < 4; ++j) s[i][j] = 0.f;
        #pragma unroll
        for (int d = 0; d < 64; ++d) {
            float a[4], bb[4];
            *(float4*)a  = *(const float4*)&Qt[d * PAD + ty * 4];
            *(float4*)bb = *(const float4*)&Kt[d * PAD + tx * 4];
            #pragma unroll
            for (int i = 0; i < 4; ++i)
                #pragma unroll
                for (int j = 0; j < 4; ++j)
                    s[i][j] = fmaf(a[i], bb[j], s[i][j]);
        }

        #pragma unroll
        for (int i = 0; i < 4; ++i) {
            const int* mrow = mask + (size_t)(q0 + ty * 4 + i) * TT + kv0 + tx * 4;
            #pragma unroll
            for (int j = 0; j < 4; ++j)
                if (mrow[j] == 0) s[i][j] = -1e30f;
        }

        #pragma unroll
        for (int i = 0; i < 4; ++i) {
            float rm = fmaxf(fmaxf(s[i][0], s[i][1]), fmaxf(s[i][2], s[i][3]));
            #pragma unroll
            for (int off = 8; off > 0; off >>= 1)
                rm = fmaxf(rm, __shfl_xor_sync(0xffffffffu, rm, off, 16));
            float m_new = fmaxf(m_i[i], rm);
            float corr  = __expf(m_i[i] - m_new);
            float psum  = 0.f;
            #pragma unroll
            for (int j = 0; j < 4; ++j) {
                float p = __expf(s[i][j] - m_new);
                s[i][j] = p;
                psum += p;
            }
            #pragma unroll
            for (int off = 8; off > 0; off >>= 1)
                psum += __shfl_xor_sync(0xffffffffu, psum, off, 16);
            l_i[i] = l_i[i] * corr + psum;
            m_i[i] = m_new;
            #pragma unroll
            for (int j = 0; j < 4; ++j) o[i][j] *= corr;
        }

        #pragma unroll
        for (int i = 0; i < 4; ++i)
            #pragma unroll
            for (int j = 0; j < 4; ++j)
                Pt[(tx * 4 + j) * PAD + ty * 4 + i] = s[i][j];
        __syncthreads();

        #pragma unroll
        for (int kk = 0; kk < 64; ++kk) {
            float a[4], bb[4];
            *(float4*)a  = *(const float4*)&Pt[kk * PAD + ty * 4];
            *(float4*)bb = *(const float4*)&Vs[kk * PAD + tx * 4];
            #pragma unroll
            for (int i = 0; i < 4; ++i)
                #pragma unroll
                for (int j = 0; j < 4; ++j)
                    o[i][j] = fmaf(a[i], bb[j], o[i][j]);
        }
    }

    #pragma unroll
    for (int i = 0; i < 4; ++i) {
        float inv = 1.f / l_i[i];
        float4 ov;
        ov.x = o[i][0] * inv; ov.y = o[i][1] * inv;
        ov.z = o[i][2] * inv; ov.w = o[i][3] * inv;
        size_t idx = (size_t)(b * TT + q0 + ty * 4 + i) * DD + h * HD + tx * 4;
        *reinterpret_cast<float4*>(y + idx) = ov;
    }
}

// ---------------------------------------------------------------------------
extern "C" void kernel_launch(void* const* d_in, const int* in_sizes, int n_in,
                              void* d_out, int out_size)
{
    const float* x     = (const float*)d_in[0];
    const int*   mask  = (const int*)d_in[1];
    const float* w_qkv = (const float*)d_in[2];
    const float* b_qkv = (const float*)d_in[3];
    const float* w_out = (const float*)d_in[4];
    const float* b_out = (const float*)d_in[5];
    float* out = (float*)d_out;

    float *qkv, *y;
    __nv_bfloat16 *xh, *xl, *wqh, *wql, *woh, *wol, *yh, *yl;
    cudaGetSymbolAddress((void**)&qkv, g_qkv);
    cudaGetSymbolAddress((void**)&y, g_y);
    cudaGetSymbolAddress((void**)&xh, g_x_hi);
    cudaGetSymbolAddress((void**)&xl, g_x_lo);
    cudaGetSymbolAddress((void**)&wqh, g_wqkv_hi);
    cudaGetSymbolAddress((void**)&wql, g_wqkv_lo);
    cudaGetSymbolAddress((void**)&woh, g_wout_hi);
    cudaGetSymbolAddress((void**)&wol, g_wout_lo);
    cudaGetSymbolAddress((void**)&yh, g_y_hi);
    cudaGetSymbolAddress((void**)&yl, g_y_lo);

    cudaFuncSetAttribute(gemm_mma_split,
                         cudaFuncAttributeMaxDynamicSharedMemorySize, GEMM_SMEM);

    // split inputs / weights
    {
        int n4 = MM * DD / 4;
        split_bf16<<<(n4 + 255) / 256, 256>>>(x, xh, xl, n4);
        n4 = 3 * DD * DD / 4;
        split_bf16<<<(n4 + 255) / 256, 256>>>(w_qkv, wqh, wql, n4);
        n4 = DD * DD / 4;
        split_bf16<<<(n4 + 255) / 256, 256>>>(w_out, woh, wol, n4);
    }

    // 1) QKV projection (tensor cores via mma.sync)
    gemm_mma_split<<<dim3(3 * DD / 128, MM / 128), 256, GEMM_SMEM>>>(
        xh, xl, wqh, wql, b_qkv, qkv, MM, 3 * DD, DD);

    // 2) fused flash attention (fp32)
    const int attn_smem = 4 * 64 * 68 * (int)sizeof(float);
    cudaFuncSetAttribute(attn_kernel,
                         cudaFuncAttributeMaxDynamicSharedMemorySize, attn_smem);
    attn_kernel<<<dim3(TT / 64, BB * HH), 256, attn_smem>>>(qkv, mask, y);

    // split attention output
    {
        int n4 = MM * DD / 4;
        split_bf16<<<(n4 + 255) / 256, 256>>>(y, yh, yl, n4);
    }

    // 3) output projection (tensor cores via mma.sync)
    gemm_mma_split<<<dim3(DD / 128, MM / 128), 256, GEMM_SMEM>>>(
        yh, yl, woh, wol, b_out, out, MM, DD, DD);
}

// round 4
// speedup vs baseline: 2.4439x; 1.9024x over previous
#include <cuda_runtime.h>
#include <cuda_bf16.h>
#include <cstdint>
#include <cstddef>

#define BB 2
#define TT 2048
#define DD 1024
#define HH 16
#define HD 64
#define MM (BB*TT)

// ---------------- scratch (allocation-free) ----------------
__device__ __nv_bfloat16 g_x_hi[(size_t)MM * DD];
__device__ __nv_bfloat16 g_x_lo[(size_t)MM * DD];
__device__ __nv_bfloat16 g_wqkv_hi[(size_t)3 * DD * DD];
__device__ __nv_bfloat16 g_wqkv_lo[(size_t)3 * DD * DD];
__device__ __nv_bfloat16 g_wout_hi[(size_t)DD * DD];
__device__ __nv_bfloat16 g_wout_lo[(size_t)DD * DD];
__device__ __nv_bfloat16 g_qkv_hi[(size_t)MM * 3 * DD];
__device__ __nv_bfloat16 g_qkv_lo[(size_t)MM * 3 * DD];
__device__ __nv_bfloat16 g_y_hi[(size_t)MM * DD];
__device__ __nv_bfloat16 g_y_lo[(size_t)MM * DD];
__device__ int g_mask_flag;

// ---------------- base-target PTX helpers ----------------
__device__ __forceinline__ uint32_t smem_u32(const void* p) {
    uint32_t a;
    asm("{ .reg .u64 t; cvta.to.shared.u64 t, %1; cvt.u32.u64 %0, t; }"
        : "=r"(a) : "l"(p));
    return a;
}
__device__ __forceinline__ void cp_async16(uint32_t dst, const void* src) {
    asm volatile("cp.async.cg.shared.global [%0], [%1], 16;"
                 :: "r"(dst), "l"(src) : "memory");
}
__device__ __forceinline__ void cp_commit() {
    asm volatile("cp.async.commit_group;" ::: "memory");
}
__device__ __forceinline__ void cp_wait0() {
    asm volatile("cp.async.wait_group 0;" ::: "memory");
}
__device__ __forceinline__ void cp_wait1() {
    asm volatile("cp.async.wait_group 1;" ::: "memory");
}
__device__ __forceinline__ void ldsm_x4(uint32_t addr, uint32_t r[4]) {
    asm volatile("ldmatrix.sync.aligned.m8n8.x4.shared.b16 {%0,%1,%2,%3}, [%4];"
                 : "=r"(r[0]), "=r"(r[1]), "=r"(r[2]), "=r"(r[3]) : "r"(addr));
}
__device__ __forceinline__ void ldsm_x4_t(uint32_t addr, uint32_t r[4]) {
    asm volatile("ldmatrix.sync.aligned.m8n8.x4.trans.shared.b16 {%0,%1,%2,%3}, [%4];"
                 : "=r"(r[0]), "=r"(r[1]), "=r"(r[2]), "=r"(r[3]) : "r"(addr));
}
__device__ __forceinline__ void mma_bf16(float d[4], const uint32_t a[4],
                                         uint32_t b0, uint32_t b1) {
    asm volatile(
        "mma.sync.aligned.m16n8k16.row.col.f32.bf16.bf16.f32 "
        "{%0,%1,%2,%3}, {%4,%5,%6,%7}, {%8,%9}, {%0,%1,%2,%3};"
        : "+f"(d[0]), "+f"(d[1]), "+f"(d[2]), "+f"(d[3])
        : "r"(a[0]), "r"(a[1]), "r"(a[2]), "r"(a[3]), "r"(b0), "r"(b1));
}
__device__ __forceinline__ uint32_t pack_hi2(float a, float b, float& ra, float& rb) {
    __nv_bfloat162 h = __floats2bfloat162_rn(a, b);
    ra = a - __bfloat162float(h.x);
    rb = b - __bfloat162float(h.y);
    return *reinterpret_cast<uint32_t*>(&h);
}
__device__ __forceinline__ uint32_t pack_bf2(float a, float b) {
    __nv_bfloat162 h = __floats2bfloat162_rn(a, b);
    return *reinterpret_cast<uint32_t*>(&h);
}

// ---------------------------------------------------------------------------
// Split fp32 -> (hi, lo) bf16
// ---------------------------------------------------------------------------
__global__ void __launch_bounds__(256) split_bf16(
    const float* __restrict__ src,
    __nv_bfloat16* __restrict__ hi, __nv_bfloat16* __restrict__ lo, int n4)
{
    int i = blockIdx.x * blockDim.x + threadIdx.x;
    if (i >= n4) return;
    float4 v = reinterpret_cast<const float4*>(src)[i];
    __nv_bfloat16 h0 = __float2bfloat16(v.x);
    __nv_bfloat16 h1 = __float2bfloat16(v.y);
    __nv_bfloat16 h2 = __float2bfloat16(v.z);
    __nv_bfloat16 h3 = __float2bfloat16(v.w);
    __nv_bfloat16 l0 = __float2bfloat16(v.x - __bfloat162float(h0));
    __nv_bfloat16 l1 = __float2bfloat16(v.y - __bfloat162float(h1));
    __nv_bfloat16 l2 = __float2bfloat16(v.z - __bfloat162float(h2));
    __nv_bfloat16 l3 = __float2bfloat16(v.w - __bfloat162float(h3));
    reinterpret_cast<__nv_bfloat162*>(hi)[i * 2 + 0] = __nv_bfloat162(h0, h1);
    reinterpret_cast<__nv_bfloat162*>(hi)[i * 2 + 1] = __nv_bfloat162(h2, h3);
    reinterpret_cast<__nv_bfloat162*>(lo)[i * 2 + 0] = __nv_bfloat162(l0, l1);
    reinterpret_cast<__nv_bfloat162*>(lo)[i * 2 + 1] = __nv_bfloat162(l2, l3);
}

// ---------------------------------------------------------------------------
// Mask all-ones check
// ---------------------------------------------------------------------------
__global__ void mask_flag_init() { g_mask_flag = 1; }
__global__ void __launch_bounds__(256) mask_reduce(const int* __restrict__ mask, int n4) {
    int i = blockIdx.x * blockDim.x + threadIdx.x;
    if (i >= n4) return;
    int4 v = reinterpret_cast<const int4*>(mask)[i];
    if (v.x == 0 || v.y == 0 || v.z == 0 || v.w == 0) g_mask_flag = 0;
}

// ---------------------------------------------------------------------------
// Split-bf16 mma.sync GEMM: C = (Ah+Al)(Bh+Bl)^T + bias   (drops Al@Bl)
// If Chi != nullptr, writes hi/lo bf16 split of C instead of fp32.
// ---------------------------------------------------------------------------
#define LDA 40
#define TILE_B (128 * LDA * 2)
#define BUF_B  (4 * TILE_B)
#define GEMM_SMEM (2 * BUF_B)

__global__ void __launch_bounds__(256)
gemm_mma_split(const __nv_bfloat16* __restrict__ Ah, const __nv_bfloat16* __restrict__ Al,
               const __nv_bfloat16* __restrict__ Bh, const __nv_bfloat16* __restrict__ Bl,
               const float* __restrict__ bias, float* __restrict__ C,
               __nv_bfloat16* __restrict__ Chi, __nv_bfloat16* __restrict__ Clo,
               int M, int N, int K)
{
    extern __shared__ __align__(16) char sm[];
    const uint32_t sm_u = smem_u32(sm);

    const int tid  = threadIdx.x;
    const int lane = tid & 31;
    const int wid  = tid >> 5;
    const int wm   = wid & 1;
    const int wn   = wid >> 1;
    const int row0 = blockIdx.y * 128;
    const int col0 = blockIdx.x * 128;

    auto copy_chunk = [&](int ch, int b) {
        const int k0 = ch * 32;
        const uint32_t base = sm_u + b * BUF_B;
        const __nv_bfloat16* srcs[4] = {Ah, Al, Bh, Bl};
        const int rbase[4] = {row0, row0, col0, col0};
        #pragma unroll
        for (int t = 0; t < 4; ++t) {
            #pragma unroll
            for (int it = 0; it < 2; ++it) {
                int idx = tid + it * 256;
                int r = idx >> 2;
                int s = idx & 3;
                cp_async16(base + t * TILE_B + r * (LDA * 2) + s * 16,
                           srcs[t] + (size_t)(rbase[t] + r) * K + k0 + s * 8);
            }
        }
    };

    float acc[4][4][4];
    #pragma unroll
    for (int i = 0; i < 4; ++i)
        #pragma unroll
        for (int j = 0; j < 4; ++j)
            #pragma unroll
            for (int r = 0; r < 4; ++r) acc[i][j][r] = 0.f;

    const int nchunk = K / 32;
    copy_chunk(0, 0);
    cp_commit();

    const int lr = lane & 15;
    const int lc = lane >> 4;

    for (int ch = 0; ch < nchunk; ++ch) {
        if (ch + 1 < nchunk) copy_chunk(ch + 1, (ch + 1) & 1);
        cp_commit();
        cp_wait1();
        __syncthreads();

        const uint32_t base = sm_u + (ch & 1) * BUF_B;
        const uint32_t tAh = base;
        const uint32_t tAl = base + TILE_B;
        const uint32_t tBh = base + 2 * TILE_B;
        const uint32_t tBl = base + 3 * TILE_B;

        #pragma unroll
        for (int kk = 0; kk < 32; kk += 16) {
            uint32_t ah[4][4], al[4][4];
            uint32_t bh[4][2], bl[4][2];
            #pragma unroll
            for (int mi = 0; mi < 4; ++mi) {
                uint32_t off = (uint32_t)((wm * 64 + mi * 16 + lr) * (LDA * 2)
                                          + (lc * 8 + kk) * 2);
                ldsm_x4(tAh + off, ah[mi]);
                ldsm_x4(tAl + off, al[mi]);
            }
            #pragma unroll
            for (int n2 = 0; n2 < 2; ++n2) {
                uint32_t off = (uint32_t)((wn * 32 + n2 * 16 + lr) * (LDA * 2)
                                          + (lc * 8 + kk) * 2);
                uint32_t th[4], tl[4];
                ldsm_x4(tBh + off, th);
                ldsm_x4(tBl + off, tl);
                bh[n2 * 2 + 0][0] = th[0]; bh[n2 * 2 + 0][1] = th[2];
                bh[n2 * 2 + 1][0] = th[1]; bh[n2 * 2 + 1][1] = th[3];
                bl[n2 * 2 + 0][0] = tl[0]; bl[n2 * 2 + 0][1] = tl[2];
                bl[n2 * 2 + 1][0] = tl[1]; bl[n2 * 2 + 1][1] = tl[3];
            }
            #pragma unroll
            for (int mi = 0; mi < 4; ++mi)
                #pragma unroll
                for (int nj = 0; nj < 4; ++nj) {
                    mma_bf16(acc[mi][nj], ah[mi], bh[nj][0], bh[nj][1]);
                    mma_bf16(acc[mi][nj], ah[mi], bl[nj][0], bl[nj][1]);
                    mma_bf16(acc[mi][nj], al[mi], bh[nj][0], bh[nj][1]);
                }
        }
        __syncthreads();
    }

    // epilogue
    #pragma unroll
    for (int mi = 0; mi < 4; ++mi) {
        #pragma unroll
        for (int nj = 0; nj < 4; ++nj) {
            int col = col0 + wn * 32 + nj * 8 + (lane & 3) * 2;
            float b0 = bias[col], b1 = bias[col + 1];
            #pragma unroll
            for (int h = 0; h < 2; ++h) {
                int row = row0 + wm * 64 + mi * 16 + (lane >> 2) + h * 8;
                float o0 = acc[mi][nj][h * 2 + 0] + b0;
                float o1 = acc[mi][nj][h * 2 + 1] + b1;
                if (Chi) {
                    float r0, r1;
                    uint32_t hi2 = pack_hi2(o0, o1, r0, r1);
                    uint32_t lo2 = pack_bf2(r0, r1);
                    *reinterpret_cast<uint32_t*>(Chi + (size_t)row * N + col) = hi2;
                    *reinterpret_cast<uint32_t*>(Clo + (size_t)row * N + col) = lo2;
                } else {
                    float2 o; o.x = o0; o.y = o1;
                    *reinterpret_cast<float2*>(C + (size_t)row * N + col) = o;
                }
            }
        }
    }
}

// ---------------------------------------------------------------------------
// Flash attention on tensor cores (split-bf16, 3-pass, online softmax).
// Grid: (T/128, B*H). 256 threads = 8 warps, warp w owns 16 query rows.
// kv tiles of 64, double-buffered cp.async. Outputs y split hi/lo.
// ---------------------------------------------------------------------------
#define ALD  72                    // smem row elems (64 + 8 pad)
#define AROWB (ALD * 2)            // 144 bytes
#define KV_TILE_B (64 * AROWB)     // 9216
#define KV_BUF_B  (4 * KV_TILE_B)  // 36864
#define ATTN_SMEM (2 * KV_BUF_B)   // 73728

__global__ void __launch_bounds__(256, 1)
attn_mma(const __nv_bfloat16* __restrict__ qkvh, const __nv_bfloat16* __restrict__ qkvl,
         const int* __restrict__ mask,
         __nv_bfloat16* __restrict__ yh, __nv_bfloat16* __restrict__ yl)
{
    extern __shared__ __align__(16) char sm[];
    const uint32_t sm_u = smem_u32(sm);

    const int tid  = threadIdx.x;
    const int lane = tid & 31;
    const int wid  = tid >> 5;
    const int q0   = blockIdx.x * 128;
    const int b    = blockIdx.y >> 4;
    const int h    = blockIdx.y & 15;
    const size_t RS = 3 * DD;
    const int lr = lane & 15;
    const int lc = lane >> 4;
    const int r0 = lane >> 2;

    // ---- stage Q (hi at 0, lo at 128*AROWB), then load A-fragments ----
    #pragma unroll
    for (int it = 0; it < 8; ++it) {
        int idx = tid + it * 256;          // 0..2047
        int t = idx >> 10;                 // 0=hi 1=lo
        int r = (idx >> 3) & 127;
        int s = idx & 7;
        const __nv_bfloat16* src = (t ? qkvl : qkvh)
            + (size_t)(b * TT + q0 + r) * RS + h * HD + s * 8;
        cp_async16(sm_u + t * (128 * AROWB) + r * AROWB + s * 16, src);
    }
    cp_commit();
    cp_wait0();
    __syncthreads();

    uint32_t qfh[4][4], qfl[4][4];
    #pragma unroll
    for (int ks = 0; ks < 4; ++ks) {
        uint32_t off = (uint32_t)((wid * 16 + lr) * AROWB + (lc * 8 + ks * 16) * 2);
        ldsm_x4(sm_u + off, qfh[ks]);
        ldsm_x4(sm_u + 128 * AROWB + off, qfl[ks]);
    }
    __syncthreads();   // Q staging free; kv buffers reuse this smem

    const int allones = g_mask_flag;

    auto copy_kv = [&](int ktile, int bufi) {
        const int kv0 = ktile * 64;
        const uint32_t base = sm_u + bufi * KV_BUF_B;
        #pragma unroll
        for (int it = 0; it < 8; ++it) {
            int idx = tid + it * 256;      // 0..2047
            int t = idx >> 9;              // 0=Kh 1=Kl 2=Vh 3=Vl
            int r = (idx >> 3) & 63;
            int s = idx & 7;
            const __nv_bfloat16* src = ((t & 1) ? qkvl : qkvh)
                + (size_t)(b * TT + kv0 + r) * RS + (1 + (t >> 1)) * DD + h * HD + s * 8;
            cp_async16(base + t * KV_TILE_B + r * AROWB + s * 16, src);
        }
    };

    float accO[8][4];
    #pragma unroll
    for (int n = 0; n < 8; ++n)
        #pragma unroll
        for (int r = 0; r < 4; ++r) accO[n][r] = 0.f;
    float mrow[2] = {-1e30f, -1e30f};
    float lrow[2] = {0.f, 0.f};

    copy_kv(0, 0);
    cp_commit();

    const int NKV = TT / 64;
    for (int kt = 0; kt < NKV; ++kt) {
        if (kt + 1 < NKV) copy_kv(kt + 1, (kt + 1) & 1);
        cp_commit();
        cp_wait1();
        __syncthreads();

        const uint32_t base = sm_u + (kt & 1) * KV_BUF_B;
        const uint32_t tKh = base;
        const uint32_t tKl = base + KV_TILE_B;
        const uint32_t tVh = base + 2 * KV_TILE_B;
        const uint32_t tVl = base + 3 * KV_TILE_B;

        // ---- S = Q @ K^T (3-pass split) ----
        float s[8][4];
        #pragma unroll
        for (int n = 0; n < 8; ++n)
            #pragma unroll
            for (int r = 0; r < 4; ++r) s[n][r] = 0.f;

        #pragma unroll
        for (int ks = 0; ks < 4; ++ks) {
            uint32_t kh[8][2], kl[8][2];
            #pragma unroll
            for (int n2 = 0; n2 < 4; ++n2) {
                uint32_t off = (uint32_t)((n2 * 16 + lr) * AROWB + (lc * 8 + ks * 16) * 2);
                uint32_t th[4], tl[4];
                ldsm_x4(tKh + off, th);
                ldsm_x4(tKl + off, tl);
                kh[n2 * 2 + 0][0] = th[0]; kh[n2 * 2 + 0][1] = th[2];
                kh[n2 * 2 + 1][0] = th[1]; kh[n2 * 2 + 1][1] = th[3];
                kl[n2 * 2 + 0][0] = tl[0]; kl[n2 * 2 + 0][1] = tl[2];
                kl[n2 * 2 + 1][0] = tl[1]; kl[n2 * 2 + 1][1] = tl[3];
            }
            #pragma unroll
            for (int nj = 0; nj < 8; ++nj) {
                mma_bf16(s[nj], qfh[ks], kh[nj][0], kh[nj][1]);
                mma_bf16(s[nj], qfh[ks], kl[nj][0], kl[nj][1]);
                mma_bf16(s[nj], qfl[ks], kh[nj][0], kh[nj][1]);
            }
        }

        // scale
        #pragma unroll
        for (int nj = 0; nj < 8; ++nj)
            #pragma unroll
            for (int r = 0; r < 4; ++r) s[nj][r] *= 0.125f;

        // mask fallback (uniform branch; all-ones dataset skips)
        if (!allones) {
            const int kv0 = kt * 64;
            int qrow = q0 + wid * 16 + r0;
            #pragma unroll
            for (int nj = 0; nj < 8; ++nj) {
                int c = kv0 + nj * 8 + (lane & 3) * 2;
                const int* m0 = mask + (size_t)qrow * TT + c;
                const int* m1 = mask + (size_t)(qrow + 8) * TT + c;
                if (m0[0] == 0) s[nj][0] = -1e30f;
                if (m0[1] == 0) s[nj][1] = -1e30f;
                if (m1[0] == 0) s[nj][2] = -1e30f;
                if (m1[1] == 0) s[nj][3] = -1e30f;
            }
        }

        // ---- online softmax (rows r0 and r0+8; cols spread over lane&3) ----
        float rm0 = -1e30f, rm1 = -1e30f;
        #pragma unroll
        for (int nj = 0; nj < 8; ++nj) {
            rm0 = fmaxf(rm0, fmaxf(s[nj][0], s[nj][1]));
            rm1 = fmaxf(rm1, fmaxf(s[nj][2], s[nj][3]));
        }
        rm0 = fmaxf(rm0, __shfl_xor_sync(0xffffffffu, rm0, 1));
        rm0 = fmaxf(rm0, __shfl_xor_sync(0xffffffffu, rm0, 2));
        rm1 = fmaxf(rm1, __shfl_xor_sync(0xffffffffu, rm1, 1));
        rm1 = fmaxf(rm1, __shfl_xor_sync(0xffffffffu, rm1, 2));

        float mn0 = fmaxf(mrow[0], rm0);
        float mn1 = fmaxf(mrow[1], rm1);
        float c0 = __expf(mrow[0] - mn0);
        float c1 = __expf(mrow[1] - mn1);
        float ps0 = 0.f, ps1 = 0.f;
        #pragma unroll
        for (int nj = 0; nj < 8; ++nj) {
            s[nj][0] = __expf(s[nj][0] - mn0);
            s[nj][1] = __expf(s[nj][1] - mn0);
            s[nj][2] = __expf(s[nj][2] - mn1);
            s[nj][3] = __expf(s[nj][3] - mn1);
            ps0 += s[nj][0] + s[nj][1];
            ps1 += s[nj][2] + s[nj][3];
        }
        ps0 += __shfl_xor_sync(0xffffffffu, ps0, 1);
        ps0 += __shfl_xor_sync(0xffffffffu, ps0, 2);
        ps1 += __shfl_xor_sync(0xffffffffu, ps1, 1);
        ps1 += __shfl_xor_sync(0xffffffffu, ps1, 2);
        lrow[0] = lrow[0] * c0 + ps0;
        lrow[1] = lrow[1] * c1 + ps1;
        mrow[0] = mn0; mrow[1] = mn1;
        #pragma unroll
        for (int nj = 0; nj < 8; ++nj) {
            accO[nj][0] *= c0; accO[nj][1] *= c0;
            accO[nj][2] *= c1; accO[nj][3] *= c1;
        }

        // ---- O += P @ V (3-pass split; P frags from S c-frags) ----
        #pragma unroll
        for (int ks = 0; ks < 4; ++ks) {
            uint32_t pfh[4], pfl[4];
            {
                float ra, rb;
                pfh[0] = pack_hi2(s[2*ks][0],   s[2*ks][1],   ra, rb);
                pfl[0] = pack_bf2(ra, rb);
                pfh[1] = pack_hi2(s[2*ks][2],   s[2*ks][3],   ra, rb);
                pfl[1] = pack_bf2(ra, rb);
                pfh[2] = pack_hi2(s[2*ks+1][0], s[2*ks+1][1], ra, rb);
                pfl[2] = pack_bf2(ra, rb);
                pfh[3] = pack_hi2(s[2*ks+1][2], s[2*ks+1][3], ra, rb);
                pfl[3] = pack_bf2(ra, rb);
            }
            #pragma unroll
            for (int g = 0; g < 4; ++g) {
                uint32_t off = (uint32_t)((ks * 16 + lr) * AROWB + (lc * 8 + g * 16) * 2);
                uint32_t vh[4], vl[4];
                ldsm_x4_t(tVh + off, vh);
                ldsm_x4_t(tVl + off, vl);
                mma_bf16(accO[2*g],   pfh, vh[0], vh[1]);
                mma_bf16(accO[2*g],   pfh, vl[0], vl[1]);
                mma_bf16(accO[2*g],   pfl, vh[0], vh[1]);
                mma_bf16(accO[2*g+1], pfh, vh[2], vh[3]);
                mma_bf16(accO[2*g+1], pfh, vl[2], vl[3]);
                mma_bf16(accO[2*g+1], pfl, vh[2], vh[3]);
            }
        }
        __syncthreads();   // all warps done reading this buffer
    }

    // ---- epilogue: normalize, split hi/lo, store y ----
    float inv0 = 1.f / lrow[0];
    float inv1 = 1.f / lrow[1];
    int row_a = b * TT + q0 + wid * 16 + r0;
    int row_b = row_a + 8;
    #pragma unroll
    for (int nj = 0; nj < 8; ++nj) {
        int col = h * HD + nj * 8 + (lane & 3) * 2;
        float ra, rb;
        uint32_t hi2, lo2;
        hi2 = pack_hi2(accO[nj][0] * inv0, accO[nj][1] * inv0, ra, rb);
        lo2 = pack_bf2(ra, rb);
        *reinterpret_cast<uint32_t*>(yh + (size_t)row_a * DD + col) = hi2;
        *reinterpret_cast<uint32_t*>(yl + (size_t)row_a * DD + col) = lo2;
        hi2 = pack_hi2(accO[nj][2] * inv1, accO[nj][3] * inv1, ra, rb);
        lo2 = pack_bf2(ra, rb);
        *reinterpret_cast<uint32_t*>(yh + (size_t)row_b * DD + col) = hi2;
        *reinterpret_cast<uint32_t*>(yl + (size_t)row_b * DD + col) = lo2;
    }
}

// ---------------------------------------------------------------------------
extern "C" void kernel_launch(void* const* d_in, const int* in_sizes, int n_in,
                              void* d_out, int out_size)
{
    const float* x     = (const float*)d_in[0];
    const int*   mask  = (const int*)d_in[1];
    const float* w_qkv = (const float*)d_in[2];
    const float* b_qkv = (const float*)d_in[3];
    const float* w_out = (const float*)d_in[4];
    const float* b_out = (const float*)d_in[5];
    float* out = (float*)d_out;

    __nv_bfloat16 *xh, *xl, *wqh, *wql, *woh, *wol, *qkvh, *qkvl, *yh, *yl;
    cudaGetSymbolAddress((void**)&xh, g_x_hi);
    cudaGetSymbolAddress((void**)&xl, g_x_lo);
    cudaGetSymbolAddress((void**)&wqh, g_wqkv_hi);
    cudaGetSymbolAddress((void**)&wql, g_wqkv_lo);
    cudaGetSymbolAddress((void**)&woh, g_wout_hi);
    cudaGetSymbolAddress((void**)&wol, g_wout_lo);
    cudaGetSymbolAddress((void**)&qkvh, g_qkv_hi);
    cudaGetSymbolAddress((void**)&qkvl, g_qkv_lo);
    cudaGetSymbolAddress((void**)&yh, g_y_hi);
    cudaGetSymbolAddress((void**)&yl, g_y_lo);

    cudaFuncSetAttribute(gemm_mma_split,
                         cudaFuncAttributeMaxDynamicSharedMemorySize, GEMM_SMEM);
    cudaFuncSetAttribute(attn_mma,
                         cudaFuncAttributeMaxDynamicSharedMemorySize, ATTN_SMEM);

    // splits + mask check
    {
        int n4 = MM * DD / 4;
        split_bf16<<<(n4 + 255) / 256, 256>>>(x, xh, xl, n4);
        n4 = 3 * DD * DD / 4;
        split_bf16<<<(n4 + 255) / 256, 256>>>(w_qkv, wqh, wql, n4);
        n4 = DD * DD / 4;
        split_bf16<<<(n4 + 255) / 256, 256>>>(w_out, woh, wol, n4);
        mask_flag_init<<<1, 1>>>();
        int m4 = TT * TT / 4;
        mask_reduce<<<(m4 + 255) / 256, 256>>>(mask, m4);
    }

    // 1) QKV projection -> split bf16 output
    gemm_mma_split<<<dim3(3 * DD / 128, MM / 128), 256, GEMM_SMEM>>>(
        xh, xl, wqh, wql, b_qkv, nullptr, qkvh, qkvl, MM, 3 * DD, DD);

    // 2) attention on tensor cores -> y split
    attn_mma<<<dim3(TT / 128, BB * HH), 256, ATTN_SMEM>>>(
        qkvh, qkvl, mask, yh, yl);

    // 3) output projection -> fp32 out
    gemm_mma_split<<<dim3(DD / 128, MM / 128), 256, GEMM_SMEM>>>(
        yh, yl, woh, wol, b_out, out, nullptr, nullptr, MM, DD, DD);
}